// round 10
// baseline (speedup 1.0000x reference)
#include <cuda_runtime.h>
#include <cuda_bf16.h>
#include <cstddef>
#include <cstdint>

#define BATCH 4096
#define LDIM 64
#define DDIM 256
#define MDIM 20
#define BR2 128
#define TB2 64

typedef unsigned long long u64;

// ---------------- helpers ----------------
__device__ __forceinline__ u64 ffma2(u64 a, u64 b, u64 c) {
    u64 d;
    asm("fma.rn.f32x2 %0, %1, %2, %3;" : "=l"(d) : "l"(a), "l"(b), "l"(c));
    return d;
}
__device__ __forceinline__ u64 pack2(float x, float y) {
    u64 r;
    asm("mov.b64 %0, {%1, %2};" : "=l"(r) : "f"(x), "f"(y));
    return r;
}
__device__ __forceinline__ float2 unpack2(u64 a) {
    float2 f;
    asm("mov.b64 {%0, %1}, %2;" : "=f"(f.x), "=f"(f.y) : "l"(a));
    return f;
}
__device__ __forceinline__ void cp16(uint32_t smem_dst, const void* gsrc) {
    asm volatile("cp.async.cg.shared.global [%0], [%1], 16;" :: "r"(smem_dst), "l"(gsrc));
}
#define MMA_BF16(D, A0, A1, A2, A3, B0, B1)                                   \
    asm volatile(                                                             \
        "mma.sync.aligned.m16n8k16.row.col.f32.bf16.bf16.f32 "                \
        "{%0,%1,%2,%3}, {%4,%5,%6,%7}, {%8,%9}, {%0,%1,%2,%3};"               \
        : "+f"((D)[0]), "+f"((D)[1]), "+f"((D)[2]), "+f"((D)[3])              \
        : "r"(A0), "r"(A1), "r"(A2), "r"(A3), "r"(B0), "r"(B1))

// split one float2 into bf16x2 hi + lo words
__device__ __forceinline__ void split2(float ax, float ay, uint32_t& hi, uint32_t& lo) {
    __nv_bfloat162 h = __floats2bfloat162_rn(ax, ay);
    hi = *reinterpret_cast<uint32_t*>(&h);
    __nv_bfloat162 l = __floats2bfloat162_rn(ax - __bfloat162float(h.x),
                                             ay - __bfloat162float(h.y));
    lo = *reinterpret_cast<uint32_t*>(&l);
}

// ---------------- scratch ----------------
// W packed: [p][split][n=24][k=256] bf16
__device__ __align__(16) __nv_bfloat16 g_Wb2[3 * 2 * 24 * 256];
__device__ float g_qs[(size_t)LDIM * BATCH * MDIM]; // [l][b][m]
__device__ float g_kvs[LDIM * MDIM * MDIM];
__device__ float g_ks_sum[LDIM * MDIM];
__device__ float g_ks_sum2[LDIM * MDIM];            // alpha-scaled
__device__ float g_vs_sum[LDIM * MDIM];
__device__ float g_scal[4];                         // sum_q, ssq_q, sum_k, ssq_k
__device__ float g_P[(size_t)LDIM * MDIM * DDIM];   // alpha * (kvs @ Wp)
__device__ float g_C[LDIM * DDIM];

// ---------------- kernel 0: weight split/pack + zero reductions ----------------
__global__ __launch_bounds__(256) void k_init(const float* __restrict__ Wk,
                                              const float* __restrict__ Wq,
                                              const float* __restrict__ Wv) {
    int i = blockIdx.x * 256 + threadIdx.x;
    {
        int k = i & 255;
        int t = i >> 8;
        int n = t % 24; t /= 24;
        int s = t & 1, p = t >> 1;
        const float* W = (p == 0) ? Wk : ((p == 1) ? Wq : Wv);
        float wv = (n < MDIM) ? W[k * MDIM + n] : 0.f;
        __nv_bfloat16 hi = __float2bfloat16(wv);
        g_Wb2[i] = s ? __float2bfloat16(wv - __bfloat162float(hi)) : hi;
    }
    if (i < LDIM * MDIM * MDIM) g_kvs[i] = 0.f;
    if (i < LDIM * MDIM) { g_ks_sum[i] = 0.f; g_vs_sum[i] = 0.f; }
    if (i < 4) g_scal[i] = 0.f;
}

// ---------------- kernel 1: mma.sync projections + reductions ----------------
// 256 thr (8 warps); block = (128 b-rows, one l). 3 proj stages of K=256.
// k-permuted fragments: thread qc owns physical k 4qc..4qc+3 per k16-step
// -> x via LDG.128, W fragment via single LDS.64 (stride 136 words, conflict-free).
extern __shared__ float smem1[];

// byte offsets; W row stride = 136 words; split block = 24*136*4 = 13056 B
#define WBUF_B 26112
#define O_WB0 0
#define O_WB1 26112
#define O_KT  52224              // float[128*20]
#define O_VT  62464
#define O_RED 72704              // float[32]
#define SM1_BYTES 72832

__global__ __launch_bounds__(256, 3) void k_pass1(const float* __restrict__ key,
                                                  const float* __restrict__ query,
                                                  const float* __restrict__ value,
                                                  const float* __restrict__ bk,
                                                  const float* __restrict__ bq,
                                                  const float* __restrict__ bv) {
    char* smem = reinterpret_cast<char*>(smem1);
    const int tid = threadIdx.x;
    const int w = tid >> 5, lane = tid & 31;
    const int qr = lane >> 2, qc = lane & 3;
    const int l = blockIdx.x;
    const int b0 = blockIdx.y * 128;
    uint32_t sb;
    asm("{ .reg .u64 t; cvta.to.shared.u64 t, %1; cvt.u32.u64 %0, t; }" : "=r"(sb) : "l"(smem));

    float* kt = reinterpret_cast<float*>(smem + O_KT);
    float* vt = reinterpret_cast<float*>(smem + O_VT);
    float* red = reinterpret_cast<float*>(smem + O_RED);

    const float* srcs[3] = {key, query, value};
    const float* biases[3] = {bk, bq, bv};

    // stage W for proj SP: 48 rows x 512 B, dst row stride 544 B; 1536 cp16 / 256 = 6 each
#define STAGE_W(SP, OFF) do {                                                 \
        _Pragma("unroll")                                                     \
        for (int j_ = 0; j_ < 6; j_++) {                                      \
            int idx = j_ * 256 + tid;                                         \
            int s_ = idx / 768, rem = idx % 768;                              \
            int n_ = rem >> 5, c_ = rem & 31;                                 \
            cp16(sb + (OFF) + (uint32_t)(s_ * 13056 + n_ * 544 + c_ * 16),    \
                 reinterpret_cast<const char*>(g_Wb2) +                       \
                 (((SP) * 2 + s_) * 24 + n_) * 512 + c_ * 16);                \
        }                                                                     \
        asm volatile("cp.async.commit_group;");                               \
    } while (0)

    float sk = 0.f, ssk = 0.f, sq = 0.f, ssq = 0.f;
    float acc[3][4];

    STAGE_W(0, O_WB0);

    #pragma unroll 1
    for (int p = 0; p < 3; p++) {
        asm volatile("cp.async.wait_group 0;");
        __syncthreads();            // W(p) visible; all warps done with compute(p-1)
        if (p < 2) STAGE_W(p + 1, (p & 1) ? O_WB0 : O_WB1);

        #pragma unroll
        for (int nt = 0; nt < 3; nt++)
            #pragma unroll
            for (int j = 0; j < 4; j++) acc[nt][j] = 0.f;

        const float* base0 = srcs[p] + ((size_t)(b0 + w * 16 + qr) * LDIM + l) * DDIM;
        const float* base1 = base0 + (size_t)8 * LDIM * DDIM;
        const uint32_t* wh = reinterpret_cast<const uint32_t*>(smem + ((p & 1) ? O_WB1 : O_WB0));
        const uint32_t* wl = wh + 3264;

        #pragma unroll 4
        for (int ks = 0; ks < 16; ks++) {
            const int doff = ks * 16 + 4 * qc;
            float4 xA = *reinterpret_cast<const float4*>(base0 + doff);
            float4 xB = *reinterpret_cast<const float4*>(base1 + doff);
            uint32_t ah0, al0, ah1, al1, ah2, al2, ah3, al3;
            split2(xA.x, xA.y, ah0, al0);
            split2(xB.x, xB.y, ah1, al1);
            split2(xA.z, xA.w, ah2, al2);
            split2(xB.z, xB.w, ah3, al3);
            const int kw = ks * 8 + 2 * qc;
            #pragma unroll
            for (int nt = 0; nt < 3; nt++) {
                const int bw = (nt * 8 + qr) * 136 + kw;
                uint2 bh = *reinterpret_cast<const uint2*>(wh + bw);
                uint2 bl = *reinterpret_cast<const uint2*>(wl + bw);
                MMA_BF16(acc[nt], ah0, ah1, ah2, ah3, bh.x, bh.y);
                MMA_BF16(acc[nt], al0, al1, al2, al3, bh.x, bh.y);
                MMA_BF16(acc[nt], ah0, ah1, ah2, ah3, bl.x, bl.y);
            }
        }

        // epilogue for proj p
        {
            const float* bias = biases[p];
            const int r0 = w * 16 + qr, r1 = r0 + 8;
            #pragma unroll
            for (int nt = 0; nt < 3; nt++) {
                const int c0 = nt * 8 + qc * 2;
                if (c0 < MDIM) {
                    float bb0 = __ldg(bias + c0), bb1 = __ldg(bias + c0 + 1);
                    float v00 = acc[nt][0] + bb0, v01 = acc[nt][1] + bb1;
                    float v10 = acc[nt][2] + bb0, v11 = acc[nt][3] + bb1;
                    if (p == 0) {
                        kt[r0 * MDIM + c0] = v00; kt[r0 * MDIM + c0 + 1] = v01;
                        kt[r1 * MDIM + c0] = v10; kt[r1 * MDIM + c0 + 1] = v11;
                        sk += v00 + v01 + v10 + v11;
                        ssk += v00 * v00 + v01 * v01 + v10 * v10 + v11 * v11;
                    } else if (p == 1) {
                        sq += v00 + v01 + v10 + v11;
                        ssq += v00 * v00 + v01 * v01 + v10 * v10 + v11 * v11;
                        *reinterpret_cast<float2*>(
                            g_qs + ((size_t)l * BATCH + b0 + r0) * MDIM + c0) = make_float2(v00, v01);
                        *reinterpret_cast<float2*>(
                            g_qs + ((size_t)l * BATCH + b0 + r1) * MDIM + c0) = make_float2(v10, v11);
                    } else {
                        vt[r0 * MDIM + c0] = v00; vt[r0 * MDIM + c0 + 1] = v01;
                        vt[r1 * MDIM + c0] = v10; vt[r1 * MDIM + c0 + 1] = v11;
                    }
                }
            }
        }
    }
#undef STAGE_W
    __syncthreads();

    // ---- kvs partials: warp w reduces rows 16w..16w+15; lanes<20 own m ----
    float* kvp = reinterpret_cast<float*>(smem);   // alias W region: [8][20][20]
    if (lane < MDIM) {
        u64 a[10];
        #pragma unroll
        for (int j = 0; j < 10; j++) a[j] = 0ull;
        #pragma unroll 4
        for (int rr = 0; rr < 16; rr++) {
            int r = w * 16 + rr;
            float km = kt[r * MDIM + lane];
            u64 kk = pack2(km, km);
            const u64* vrow = reinterpret_cast<const u64*>(vt + r * MDIM);
            #pragma unroll
            for (int j = 0; j < 10; j++) a[j] = ffma2(kk, vrow[j], a[j]);
        }
        float2* dst = reinterpret_cast<float2*>(kvp + (w * MDIM + lane) * MDIM);
        #pragma unroll
        for (int j = 0; j < 10; j++) dst[j] = unpack2(a[j]);
    }

    // ---- scalar stats ----
    #pragma unroll
    for (int off = 16; off; off >>= 1) {
        sk  += __shfl_down_sync(0xffffffffu, sk,  off);
        ssk += __shfl_down_sync(0xffffffffu, ssk, off);
        sq  += __shfl_down_sync(0xffffffffu, sq,  off);
        ssq += __shfl_down_sync(0xffffffffu, ssq, off);
    }
    if (lane == 0) { red[w*4+0] = sk; red[w*4+1] = ssk; red[w*4+2] = sq; red[w*4+3] = ssq; }
    __syncthreads();

    if (tid < 4) {
        float s = 0.f;
        #pragma unroll
        for (int ww = 0; ww < 8; ww++) s += red[ww * 4 + tid];
        atomicAdd(&g_scal[(tid + 2) & 3], s);   // 0=sk->2, 1=ssk->3, 2=sq->0, 3=ssq->1
    }
    for (int i = tid; i < MDIM * MDIM; i += 256) {
        float s = 0.f;
        #pragma unroll
        for (int ww = 0; ww < 8; ww++) s += kvp[ww * MDIM * MDIM + i];
        atomicAdd(&g_kvs[l * MDIM * MDIM + i], s);
    }
    if (tid < MDIM) {
        float s1 = 0.f, s2 = 0.f;
        #pragma unroll 8
        for (int r = 0; r < 128; r++) { s1 += kt[r * MDIM + tid]; s2 += vt[r * MDIM + tid]; }
        atomicAdd(&g_ks_sum[l * MDIM + tid], s1);
        atomicAdd(&g_vs_sum[l * MDIM + tid], s2);
    }
}

// ---------------- kernel 2: P = alpha*(kvs@Wp), C = vs_sum@Wp, ksum2 = alpha*ksum ----
__global__ __launch_bounds__(256) void k_mid(const float* __restrict__ Wp) {
    __shared__ float kvs_s[MDIM * MDIM];
    __shared__ float vsum_s[MDIM];
    int l = blockIdx.x, tid = threadIdx.x;
    for (int i = tid; i < MDIM * MDIM; i += 256) kvs_s[i] = g_kvs[l * MDIM * MDIM + i];
    if (tid < MDIM) vsum_s[tid] = g_vs_sum[l * MDIM + tid];
    __syncthreads();
    float sqs = g_scal[0], ssq = g_scal[1], sks = g_scal[2], ssk = g_scal[3];
    float alpha = (sqs != 0.f && sks != 0.f) ? rsqrtf(ssq) * rsqrtf(ssk) : 1.f;
    int d = tid;
    float wp[MDIM];
    #pragma unroll
    for (int m2 = 0; m2 < MDIM; m2++) wp[m2] = __ldg(Wp + m2 * DDIM + d);
    float c = 0.f;
    #pragma unroll
    for (int m2 = 0; m2 < MDIM; m2++) c += vsum_s[m2] * wp[m2];
    g_C[l * DDIM + d] = c;
    #pragma unroll 4
    for (int m = 0; m < MDIM; m++) {
        float s = 0.f;
        #pragma unroll
        for (int m2 = 0; m2 < MDIM; m2++) s += kvs_s[m * MDIM + m2] * wp[m2];
        g_P[((size_t)l * MDIM + m) * DDIM + d] = alpha * s;
    }
    if (tid < MDIM) g_ks_sum2[l * MDIM + tid] = alpha * g_ks_sum[l * MDIM + tid];
}

// ---------------- kernel 3: output; thread owns a d-pair, P (alpha-scaled) in regs ----
__global__ __launch_bounds__(256) void k_pass2(float* __restrict__ out,
                                               const float* __restrict__ bp) {
    __shared__ __align__(16) float qtile[TB2 * MDIM];
    __shared__ float sc[TB2];          // per-b: inv
    __shared__ float ksum_s[MDIM];
    const int tid = threadIdx.x;
    const int dp = tid & 127, g = tid >> 7;
    const int d0 = 2 * dp;
    const int l = blockIdx.x, b0 = blockIdx.y * BR2;

    u64 pa[10], pb[10];
    #pragma unroll
    for (int j = 0; j < 10; j++) {
        const float* P0 = g_P + ((size_t)l * MDIM + 2 * j) * DDIM + d0;
        const float* P1 = g_P + ((size_t)l * MDIM + 2 * j + 1) * DDIM + d0;
        pa[j] = pack2(P0[0], P1[0]);
        pb[j] = pack2(P0[1], P1[1]);
    }
    float C0 = g_C[l * DDIM + d0], C1 = g_C[l * DDIM + d0 + 1];
    float bp0 = __ldg(bp + d0), bp1 = __ldg(bp + d0 + 1);
    if (tid < MDIM) ksum_s[tid] = g_ks_sum2[l * MDIM + tid];

    #pragma unroll 1
    for (int t = 0; t < BR2 / TB2; t++) {
        __syncthreads();
        const size_t qbase = ((size_t)l * BATCH + b0 + t * TB2) * MDIM;
        for (int i = tid; i < TB2 * MDIM / 4; i += 256)
            *reinterpret_cast<float4*>(qtile + i * 4) =
                *reinterpret_cast<const float4*>(g_qs + qbase + i * 4);
        if (tid < TB2) {
            const float* qr = g_qs + qbase + (size_t)tid * MDIM;
            float s = 0.f;
            #pragma unroll
            for (int m = 0; m < MDIM; m++) s += __ldg(qr + m) * ksum_s[m];
            sc[tid] = 1.f / (s + (float)BATCH);
        }
        __syncthreads();

        #pragma unroll 2
        for (int bb = 0; bb < TB2 / 2; bb++) {
            const int b = g * (TB2 / 2) + bb;
            const u64* q2 = reinterpret_cast<const u64*>(qtile + b * MDIM);
            u64 a0 = 0ull, a1 = 0ull;
            #pragma unroll
            for (int j = 0; j < 10; j++) {
                a0 = ffma2(q2[j], pa[j], a0);
                a1 = ffma2(q2[j], pb[j], a1);
            }
            float2 f0 = unpack2(a0), f1 = unpack2(a1);
            float inv = sc[b];
            float o0 = fmaf(f0.x + f0.y + C0, inv, bp0);
            float o1 = fmaf(f1.x + f1.y + C1, inv, bp1);
            size_t ob = ((size_t)(b0 + t * TB2 + b) * LDIM + l) * DDIM + d0;
            *reinterpret_cast<float2*>(out + ob) = make_float2(o0, o1);
        }
    }
}

// ---------------- launch ----------------
extern "C" void kernel_launch(void* const* d_in, const int* in_sizes, int n_in,
                              void* d_out, int out_size) {
    const float* key   = (const float*)d_in[0];
    const float* value = (const float*)d_in[1];
    const float* query = (const float*)d_in[2];
    const float* Wk = (const float*)d_in[3];
    const float* bk = (const float*)d_in[4];
    const float* Wq = (const float*)d_in[5];
    const float* bq = (const float*)d_in[6];
    const float* Wv = (const float*)d_in[7];
    const float* bv = (const float*)d_in[8];
    const float* Wp = (const float*)d_in[9];
    const float* bp = (const float*)d_in[10];
    float* out = (float*)d_out;
    (void)in_sizes; (void)n_in; (void)out_size;

    cudaFuncSetAttribute(k_pass1, cudaFuncAttributeMaxDynamicSharedMemorySize, SM1_BYTES);

    k_init<<<144, 256>>>(Wk, Wq, Wv);
    k_pass1<<<dim3(LDIM, BATCH / 128), 256, SM1_BYTES>>>(key, query, value, bk, bq, bv);
    k_mid<<<LDIM, 256>>>(Wp);
    k_pass2<<<dim3(LDIM, BATCH / BR2), 256>>>(out, bp);
}

// round 14
// speedup vs baseline: 1.1315x; 1.1315x over previous
#include <cuda_runtime.h>
#include <cuda_bf16.h>
#include <cstddef>
#include <cstdint>

#define BATCH 4096
#define LDIM 64
#define DDIM 256
#define MDIM 20
#define BR2 128
#define TB2 64

typedef unsigned long long u64;

// ---------------- helpers ----------------
__device__ __forceinline__ u64 ffma2(u64 a, u64 b, u64 c) {
    u64 d;
    asm("fma.rn.f32x2 %0, %1, %2, %3;" : "=l"(d) : "l"(a), "l"(b), "l"(c));
    return d;
}
__device__ __forceinline__ u64 pack2(float x, float y) {
    u64 r;
    asm("mov.b64 %0, {%1, %2};" : "=l"(r) : "f"(x), "f"(y));
    return r;
}
__device__ __forceinline__ float2 unpack2(u64 a) {
    float2 f;
    asm("mov.b64 {%0, %1}, %2;" : "=f"(f.x), "=f"(f.y) : "l"(a));
    return f;
}
__device__ __forceinline__ void cp16(uint32_t smem_dst, const void* gsrc) {
    asm volatile("cp.async.cg.shared.global [%0], [%1], 16;" :: "r"(smem_dst), "l"(gsrc));
}
#define MMA_BF16(D, A0, A1, A2, A3, B0, B1)                                   \
    asm volatile(                                                             \
        "mma.sync.aligned.m16n8k16.row.col.f32.bf16.bf16.f32 "                \
        "{%0,%1,%2,%3}, {%4,%5,%6,%7}, {%8,%9}, {%0,%1,%2,%3};"               \
        : "+f"((D)[0]), "+f"((D)[1]), "+f"((D)[2]), "+f"((D)[3])              \
        : "r"(A0), "r"(A1), "r"(A2), "r"(A3), "r"(B0), "r"(B1))

// split one float2 into bf16x2 hi + lo words
__device__ __forceinline__ void split2(float ax, float ay, uint32_t& hi, uint32_t& lo) {
    __nv_bfloat162 h = __floats2bfloat162_rn(ax, ay);
    hi = *reinterpret_cast<uint32_t*>(&h);
    __nv_bfloat162 l = __floats2bfloat162_rn(ax - __bfloat162float(h.x),
                                             ay - __bfloat162float(h.y));
    lo = *reinterpret_cast<uint32_t*>(&l);
}

// ---------------- scratch ----------------
// W packed: [p][split][n=24][k=256] bf16
__device__ __align__(16) __nv_bfloat16 g_Wb2[3 * 2 * 24 * 256];
__device__ float g_qs[(size_t)LDIM * BATCH * MDIM]; // [l][b][m]
__device__ float g_kvs[LDIM * MDIM * MDIM];
__device__ float g_ks_sum[LDIM * MDIM];
__device__ float g_ks_sum2[LDIM * MDIM];            // alpha-scaled
__device__ float g_vs_sum[LDIM * MDIM];
__device__ float g_scal[4];                         // sum_q, ssq_q, sum_k, ssq_k
__device__ float g_P[(size_t)LDIM * MDIM * DDIM];   // alpha * (kvs @ Wp)
__device__ float g_C[LDIM * DDIM];

// ---------------- kernel 0: weight split/pack + zero reductions ----------------
__global__ __launch_bounds__(256) void k_init(const float* __restrict__ Wk,
                                              const float* __restrict__ Wq,
                                              const float* __restrict__ Wv) {
    int i = blockIdx.x * 256 + threadIdx.x;
    {
        int k = i & 255;
        int t = i >> 8;
        int n = t % 24; t /= 24;
        int s = t & 1, p = t >> 1;
        const float* W = (p == 0) ? Wk : ((p == 1) ? Wq : Wv);
        float wv = (n < MDIM) ? W[k * MDIM + n] : 0.f;
        __nv_bfloat16 hi = __float2bfloat16(wv);
        g_Wb2[i] = s ? __float2bfloat16(wv - __bfloat162float(hi)) : hi;
    }
    if (i < LDIM * MDIM * MDIM) g_kvs[i] = 0.f;
    if (i < LDIM * MDIM) { g_ks_sum[i] = 0.f; g_vs_sum[i] = 0.f; }
    if (i < 4) g_scal[i] = 0.f;
}

// ---------------- kernel 1: mma.sync projections + reductions ----------------
// 256 thr (8 warps); block = (128 b-rows, one l). 3 proj stages of K=256.
// k-permuted fragments (thread qc owns physical k 4qc..4qc+3 per k16-step):
// x via LDG.128 FRONT-BATCHED in groups of 4 k-steps (8 independent LDG in flight),
// W fragment via single LDS.64 (row stride 136 words, conflict-free).
extern __shared__ float smem1[];

// byte offsets; W row stride = 136 words; split block = 24*136*4 = 13056 B
#define WBUF_B 26112
#define O_WB0 0
#define O_WB1 26112
#define O_KT  52224              // float[128*20]
#define O_VT  62464
#define O_RED 72704              // float[32]
#define SM1_BYTES 72832

__global__ __launch_bounds__(256, 2) void k_pass1(const float* __restrict__ key,
                                                  const float* __restrict__ query,
                                                  const float* __restrict__ value,
                                                  const float* __restrict__ bk,
                                                  const float* __restrict__ bq,
                                                  const float* __restrict__ bv) {
    char* smem = reinterpret_cast<char*>(smem1);
    const int tid = threadIdx.x;
    const int w = tid >> 5, lane = tid & 31;
    const int qr = lane >> 2, qc = lane & 3;
    const int l = blockIdx.x;
    const int b0 = blockIdx.y * 128;
    uint32_t sb;
    asm("{ .reg .u64 t; cvta.to.shared.u64 t, %1; cvt.u32.u64 %0, t; }" : "=r"(sb) : "l"(smem));

    float* kt = reinterpret_cast<float*>(smem + O_KT);
    float* vt = reinterpret_cast<float*>(smem + O_VT);
    float* red = reinterpret_cast<float*>(smem + O_RED);

    const float* srcs[3] = {key, query, value};
    const float* biases[3] = {bk, bq, bv};

    // stage W for proj SP: 48 rows x 512 B, dst row stride 544 B; 1536 cp16 / 256 = 6 each
#define STAGE_W(SP, OFF) do {                                                 \
        _Pragma("unroll")                                                     \
        for (int j_ = 0; j_ < 6; j_++) {                                      \
            int idx = j_ * 256 + tid;                                         \
            int s_ = idx / 768, rem = idx % 768;                              \
            int n_ = rem >> 5, c_ = rem & 31;                                 \
            cp16(sb + (OFF) + (uint32_t)(s_ * 13056 + n_ * 544 + c_ * 16),    \
                 reinterpret_cast<const char*>(g_Wb2) +                       \
                 (((SP) * 2 + s_) * 24 + n_) * 512 + c_ * 16);                \
        }                                                                     \
        asm volatile("cp.async.commit_group;");                               \
    } while (0)

    float sk = 0.f, ssk = 0.f, sq = 0.f, ssq = 0.f;
    float acc[3][4];

    STAGE_W(0, O_WB0);

    #pragma unroll 1
    for (int p = 0; p < 3; p++) {
        asm volatile("cp.async.wait_group 0;");
        __syncthreads();            // W(p) visible; all warps done with compute(p-1)
        if (p < 2) STAGE_W(p + 1, (p & 1) ? O_WB0 : O_WB1);

        #pragma unroll
        for (int nt = 0; nt < 3; nt++)
            #pragma unroll
            for (int j = 0; j < 4; j++) acc[nt][j] = 0.f;

        const float* base0 = srcs[p] + ((size_t)(b0 + w * 16 + qr) * LDIM + l) * DDIM;
        const float* base1 = base0 + (size_t)8 * LDIM * DDIM;
        const uint32_t* wh = reinterpret_cast<const uint32_t*>(smem + ((p & 1) ? O_WB1 : O_WB0));
        const uint32_t* wl = wh + 3264;

        #pragma unroll 1
        for (int ks4 = 0; ks4 < 4; ks4++) {
            // front-batch 8 independent LDG.128 for 4 k-steps
            float4 xA[4], xB[4];
            #pragma unroll
            for (int i = 0; i < 4; i++) {
                const int doff = (ks4 * 4 + i) * 16 + 4 * qc;
                xA[i] = *reinterpret_cast<const float4*>(base0 + doff);
                xB[i] = *reinterpret_cast<const float4*>(base1 + doff);
            }
            #pragma unroll
            for (int i = 0; i < 4; i++) {
                uint32_t ah0, al0, ah1, al1, ah2, al2, ah3, al3;
                split2(xA[i].x, xA[i].y, ah0, al0);
                split2(xB[i].x, xB[i].y, ah1, al1);
                split2(xA[i].z, xA[i].w, ah2, al2);
                split2(xB[i].z, xB[i].w, ah3, al3);
                const int kw = (ks4 * 4 + i) * 8 + 2 * qc;
                #pragma unroll
                for (int nt = 0; nt < 3; nt++) {
                    const int bw = (nt * 8 + qr) * 136 + kw;
                    uint2 bh = *reinterpret_cast<const uint2*>(wh + bw);
                    uint2 bl = *reinterpret_cast<const uint2*>(wl + bw);
                    MMA_BF16(acc[nt], ah0, ah1, ah2, ah3, bh.x, bh.y);
                    MMA_BF16(acc[nt], al0, al1, al2, al3, bh.x, bh.y);
                    MMA_BF16(acc[nt], ah0, ah1, ah2, ah3, bl.x, bl.y);
                }
            }
        }

        // epilogue for proj p
        {
            const float* bias = biases[p];
            const int r0 = w * 16 + qr, r1 = r0 + 8;
            #pragma unroll
            for (int nt = 0; nt < 3; nt++) {
                const int c0 = nt * 8 + qc * 2;
                if (c0 < MDIM) {
                    float bb0 = __ldg(bias + c0), bb1 = __ldg(bias + c0 + 1);
                    float v00 = acc[nt][0] + bb0, v01 = acc[nt][1] + bb1;
                    float v10 = acc[nt][2] + bb0, v11 = acc[nt][3] + bb1;
                    if (p == 0) {
                        kt[r0 * MDIM + c0] = v00; kt[r0 * MDIM + c0 + 1] = v01;
                        kt[r1 * MDIM + c0] = v10; kt[r1 * MDIM + c0 + 1] = v11;
                        sk += v00 + v01 + v10 + v11;
                        ssk += v00 * v00 + v01 * v01 + v10 * v10 + v11 * v11;
                    } else if (p == 1) {
                        sq += v00 + v01 + v10 + v11;
                        ssq += v00 * v00 + v01 * v01 + v10 * v10 + v11 * v11;
                        *reinterpret_cast<float2*>(
                            g_qs + ((size_t)l * BATCH + b0 + r0) * MDIM + c0) = make_float2(v00, v01);
                        *reinterpret_cast<float2*>(
                            g_qs + ((size_t)l * BATCH + b0 + r1) * MDIM + c0) = make_float2(v10, v11);
                    } else {
                        vt[r0 * MDIM + c0] = v00; vt[r0 * MDIM + c0 + 1] = v01;
                        vt[r1 * MDIM + c0] = v10; vt[r1 * MDIM + c0 + 1] = v11;
                    }
                }
            }
        }
    }
#undef STAGE_W
    __syncthreads();

    // ---- kvs partials: warp w reduces rows 16w..16w+15; lanes<20 own m ----
    float* kvp = reinterpret_cast<float*>(smem);   // alias W region: [8][20][20]
    if (lane < MDIM) {
        u64 a[10];
        #pragma unroll
        for (int j = 0; j < 10; j++) a[j] = 0ull;
        #pragma unroll 4
        for (int rr = 0; rr < 16; rr++) {
            int r = w * 16 + rr;
            float km = kt[r * MDIM + lane];
            u64 kk = pack2(km, km);
            const u64* vrow = reinterpret_cast<const u64*>(vt + r * MDIM);
            #pragma unroll
            for (int j = 0; j < 10; j++) a[j] = ffma2(kk, vrow[j], a[j]);
        }
        float2* dst = reinterpret_cast<float2*>(kvp + (w * MDIM + lane) * MDIM);
        #pragma unroll
        for (int j = 0; j < 10; j++) dst[j] = unpack2(a[j]);
    }

    // ---- scalar stats ----
    #pragma unroll
    for (int off = 16; off; off >>= 1) {
        sk  += __shfl_down_sync(0xffffffffu, sk,  off);
        ssk += __shfl_down_sync(0xffffffffu, ssk, off);
        sq  += __shfl_down_sync(0xffffffffu, sq,  off);
        ssq += __shfl_down_sync(0xffffffffu, ssq, off);
    }
    if (lane == 0) { red[w*4+0] = sk; red[w*4+1] = ssk; red[w*4+2] = sq; red[w*4+3] = ssq; }
    __syncthreads();

    if (tid < 4) {
        float s = 0.f;
        #pragma unroll
        for (int ww = 0; ww < 8; ww++) s += red[ww * 4 + tid];
        atomicAdd(&g_scal[(tid + 2) & 3], s);   // 0=sk->2, 1=ssk->3, 2=sq->0, 3=ssq->1
    }
    for (int i = tid; i < MDIM * MDIM; i += 256) {
        float s = 0.f;
        #pragma unroll
        for (int ww = 0; ww < 8; ww++) s += kvp[ww * MDIM * MDIM + i];
        atomicAdd(&g_kvs[l * MDIM * MDIM + i], s);
    }
    if (tid < MDIM) {
        float s1 = 0.f, s2 = 0.f;
        #pragma unroll 8
        for (int r = 0; r < 128; r++) { s1 += kt[r * MDIM + tid]; s2 += vt[r * MDIM + tid]; }
        atomicAdd(&g_ks_sum[l * MDIM + tid], s1);
        atomicAdd(&g_vs_sum[l * MDIM + tid], s2);
    }
}

// ---------------- kernel 2: P = alpha*(kvs@Wp), C = vs_sum@Wp, ksum2 = alpha*ksum ----
__global__ __launch_bounds__(256) void k_mid(const float* __restrict__ Wp) {
    __shared__ float kvs_s[MDIM * MDIM];
    __shared__ float vsum_s[MDIM];
    int l = blockIdx.x, tid = threadIdx.x;
    for (int i = tid; i < MDIM * MDIM; i += 256) kvs_s[i] = g_kvs[l * MDIM * MDIM + i];
    if (tid < MDIM) vsum_s[tid] = g_vs_sum[l * MDIM + tid];
    __syncthreads();
    float sqs = g_scal[0], ssq = g_scal[1], sks = g_scal[2], ssk = g_scal[3];
    float alpha = (sqs != 0.f && sks != 0.f) ? rsqrtf(ssq) * rsqrtf(ssk) : 1.f;
    int d = tid;
    float wp[MDIM];
    #pragma unroll
    for (int m2 = 0; m2 < MDIM; m2++) wp[m2] = __ldg(Wp + m2 * DDIM + d);
    float c = 0.f;
    #pragma unroll
    for (int m2 = 0; m2 < MDIM; m2++) c += vsum_s[m2] * wp[m2];
    g_C[l * DDIM + d] = c;
    #pragma unroll 4
    for (int m = 0; m < MDIM; m++) {
        float s = 0.f;
        #pragma unroll
        for (int m2 = 0; m2 < MDIM; m2++) s += kvs_s[m * MDIM + m2] * wp[m2];
        g_P[((size_t)l * MDIM + m) * DDIM + d] = alpha * s;
    }
    if (tid < MDIM) g_ks_sum2[l * MDIM + tid] = alpha * g_ks_sum[l * MDIM + tid];
}

// ---------------- kernel 3: output; thread owns a d-pair, P (alpha-scaled) in regs ----
__global__ __launch_bounds__(256) void k_pass2(float* __restrict__ out,
                                               const float* __restrict__ bp) {
    __shared__ __align__(16) float qtile[TB2 * MDIM];
    __shared__ float sc[TB2];          // per-b: inv
    __shared__ float ksum_s[MDIM];
    const int tid = threadIdx.x;
    const int dp = tid & 127, g = tid >> 7;
    const int d0 = 2 * dp;
    const int l = blockIdx.x, b0 = blockIdx.y * BR2;

    u64 pa[10], pb[10];
    #pragma unroll
    for (int j = 0; j < 10; j++) {
        const float* P0 = g_P + ((size_t)l * MDIM + 2 * j) * DDIM + d0;
        const float* P1 = g_P + ((size_t)l * MDIM + 2 * j + 1) * DDIM + d0;
        pa[j] = pack2(P0[0], P1[0]);
        pb[j] = pack2(P0[1], P1[1]);
    }
    float C0 = g_C[l * DDIM + d0], C1 = g_C[l * DDIM + d0 + 1];
    float bp0 = __ldg(bp + d0), bp1 = __ldg(bp + d0 + 1);
    if (tid < MDIM) ksum_s[tid] = g_ks_sum2[l * MDIM + tid];

    #pragma unroll 1
    for (int t = 0; t < BR2 / TB2; t++) {
        __syncthreads();
        const size_t qbase = ((size_t)l * BATCH + b0 + t * TB2) * MDIM;
        for (int i = tid; i < TB2 * MDIM / 4; i += 256)
            *reinterpret_cast<float4*>(qtile + i * 4) =
                *reinterpret_cast<const float4*>(g_qs + qbase + i * 4);
        if (tid < TB2) {
            const float* qr = g_qs + qbase + (size_t)tid * MDIM;
            float s = 0.f;
            #pragma unroll
            for (int m = 0; m < MDIM; m++) s += __ldg(qr + m) * ksum_s[m];
            sc[tid] = 1.f / (s + (float)BATCH);
        }
        __syncthreads();

        #pragma unroll 2
        for (int bb = 0; bb < TB2 / 2; bb++) {
            const int b = g * (TB2 / 2) + bb;
            const u64* q2 = reinterpret_cast<const u64*>(qtile + b * MDIM);
            u64 a0 = 0ull, a1 = 0ull;
            #pragma unroll
            for (int j = 0; j < 10; j++) {
                a0 = ffma2(q2[j], pa[j], a0);
                a1 = ffma2(q2[j], pb[j], a1);
            }
            float2 f0 = unpack2(a0), f1 = unpack2(a1);
            float inv = sc[b];
            float o0 = fmaf(f0.x + f0.y + C0, inv, bp0);
            float o1 = fmaf(f1.x + f1.y + C1, inv, bp1);
            size_t ob = ((size_t)(b0 + t * TB2 + b) * LDIM + l) * DDIM + d0;
            *reinterpret_cast<float2*>(out + ob) = make_float2(o0, o1);
        }
    }
}

// ---------------- launch ----------------
extern "C" void kernel_launch(void* const* d_in, const int* in_sizes, int n_in,
                              void* d_out, int out_size) {
    const float* key   = (const float*)d_in[0];
    const float* value = (const float*)d_in[1];
    const float* query = (const float*)d_in[2];
    const float* Wk = (const float*)d_in[3];
    const float* bk = (const float*)d_in[4];
    const float* Wq = (const float*)d_in[5];
    const float* bq = (const float*)d_in[6];
    const float* Wv = (const float*)d_in[7];
    const float* bv = (const float*)d_in[8];
    const float* Wp = (const float*)d_in[9];
    const float* bp = (const float*)d_in[10];
    float* out = (float*)d_out;
    (void)in_sizes; (void)n_in; (void)out_size;

    cudaFuncSetAttribute(k_pass1, cudaFuncAttributeMaxDynamicSharedMemorySize, SM1_BYTES);

    k_init<<<144, 256>>>(Wk, Wq, Wv);
    k_pass1<<<dim3(LDIM, BATCH / 128), 256, SM1_BYTES>>>(key, query, value, bk, bq, bv);
    k_mid<<<LDIM, 256>>>(Wp);
    k_pass2<<<dim3(LDIM, BATCH / BR2), 256>>>(out, bp);
}

// round 17
// speedup vs baseline: 1.1771x; 1.0403x over previous
#include <cuda_runtime.h>
#include <cuda_bf16.h>
#include <cstddef>
#include <cstdint>

#define BATCH 4096
#define LDIM 64
#define DDIM 256
#define MDIM 20

typedef unsigned long long u64;

// ---------------- helpers ----------------
__device__ __forceinline__ u64 ffma2(u64 a, u64 b, u64 c) {
    u64 d;
    asm("fma.rn.f32x2 %0, %1, %2, %3;" : "=l"(d) : "l"(a), "l"(b), "l"(c));
    return d;
}
__device__ __forceinline__ u64 pack2(float x, float y) {
    u64 r;
    asm("mov.b64 %0, {%1, %2};" : "=l"(r) : "f"(x), "f"(y));
    return r;
}
__device__ __forceinline__ float2 unpack2(u64 a) {
    float2 f;
    asm("mov.b64 {%0, %1}, %2;" : "=f"(f.x), "=f"(f.y) : "l"(a));
    return f;
}
__device__ __forceinline__ void cp16(uint32_t smem_dst, const void* gsrc) {
    asm volatile("cp.async.cg.shared.global [%0], [%1], 16;" :: "r"(smem_dst), "l"(gsrc));
}
#define MMA_BF16(D, A0, A1, A2, A3, B0, B1)                                   \
    asm volatile(                                                             \
        "mma.sync.aligned.m16n8k16.row.col.f32.bf16.bf16.f32 "                \
        "{%0,%1,%2,%3}, {%4,%5,%6,%7}, {%8,%9}, {%0,%1,%2,%3};"               \
        : "+f"((D)[0]), "+f"((D)[1]), "+f"((D)[2]), "+f"((D)[3])              \
        : "r"(A0), "r"(A1), "r"(A2), "r"(A3), "r"(B0), "r"(B1))

// split one float2 into bf16x2 hi + lo words
__device__ __forceinline__ void split2(float ax, float ay, uint32_t& hi, uint32_t& lo) {
    __nv_bfloat162 h = __floats2bfloat162_rn(ax, ay);
    hi = *reinterpret_cast<uint32_t*>(&h);
    __nv_bfloat162 l = __floats2bfloat162_rn(ax - __bfloat162float(h.x),
                                             ay - __bfloat162float(h.y));
    lo = *reinterpret_cast<uint32_t*>(&l);
}

// ---------------- scratch ----------------
// W packed: [p][split][n=24][k=256] bf16
__device__ __align__(16) __nv_bfloat16 g_Wb2[3 * 2 * 24 * 256];
// qs bf16 hi/lo: [l][b][m=20] (+pad for fragment overreads)
__device__ __align__(16) __nv_bfloat16 g_qsh[(size_t)LDIM * BATCH * MDIM + 32];
__device__ __align__(16) __nv_bfloat16 g_qsl[(size_t)LDIM * BATCH * MDIM + 32];
__device__ float g_kvs[LDIM * MDIM * MDIM];
__device__ float g_ks_sum[LDIM * MDIM];
__device__ float g_vs_sum[LDIM * MDIM];
__device__ float g_scal[4];                         // sum_q, ssq_q, sum_k, ssq_k
// P as MMA B-tiles: [l][split][kstep][row=264][16 bf16]; row 256 = alpha*ks_sum
__device__ __align__(16) __nv_bfloat16 g_Pbf[(size_t)LDIM * 2 * 2 * 264 * 16];
__device__ float g_C[LDIM * DDIM];

// ---------------- kernel 0: weight split/pack + zero reductions ----------------
__global__ __launch_bounds__(256) void k_init(const float* __restrict__ Wk,
                                              const float* __restrict__ Wq,
                                              const float* __restrict__ Wv) {
    int i = blockIdx.x * 256 + threadIdx.x;
    {
        int k = i & 255;
        int t = i >> 8;
        int n = t % 24; t /= 24;
        int s = t & 1, p = t >> 1;
        const float* W = (p == 0) ? Wk : ((p == 1) ? Wq : Wv);
        float wv = (n < MDIM) ? W[k * MDIM + n] : 0.f;
        __nv_bfloat16 hi = __float2bfloat16(wv);
        g_Wb2[i] = s ? __float2bfloat16(wv - __bfloat162float(hi)) : hi;
    }
    if (i < LDIM * MDIM * MDIM) g_kvs[i] = 0.f;
    if (i < LDIM * MDIM) { g_ks_sum[i] = 0.f; g_vs_sum[i] = 0.f; }
    if (i < 4) g_scal[i] = 0.f;
}

// ---------------- kernel 1: mma.sync projections + reductions ----------------
extern __shared__ float smem1[];

#define O_WB0 0
#define O_WB1 26112
#define O_KT  52224              // float[128*20]
#define O_VT  62464
#define O_RED 72704              // float[32]
#define SM1_BYTES 72832

__global__ __launch_bounds__(256, 2) void k_pass1(const float* __restrict__ key,
                                                  const float* __restrict__ query,
                                                  const float* __restrict__ value,
                                                  const float* __restrict__ bk,
                                                  const float* __restrict__ bq,
                                                  const float* __restrict__ bv) {
    char* smem = reinterpret_cast<char*>(smem1);
    const int tid = threadIdx.x;
    const int w = tid >> 5, lane = tid & 31;
    const int qr = lane >> 2, qc = lane & 3;
    const int l = blockIdx.x;
    const int b0 = blockIdx.y * 128;
    uint32_t sb;
    asm("{ .reg .u64 t; cvta.to.shared.u64 t, %1; cvt.u32.u64 %0, t; }" : "=r"(sb) : "l"(smem));

    float* kt = reinterpret_cast<float*>(smem + O_KT);
    float* vt = reinterpret_cast<float*>(smem + O_VT);
    float* red = reinterpret_cast<float*>(smem + O_RED);

    const float* srcs[3] = {key, query, value};
    const float* biases[3] = {bk, bq, bv};

#define STAGE_W(SP, OFF) do {                                                 \
        _Pragma("unroll")                                                     \
        for (int j_ = 0; j_ < 6; j_++) {                                      \
            int idx = j_ * 256 + tid;                                         \
            int s_ = idx / 768, rem = idx % 768;                              \
            int n_ = rem >> 5, c_ = rem & 31;                                 \
            cp16(sb + (OFF) + (uint32_t)(s_ * 13056 + n_ * 544 + c_ * 16),    \
                 reinterpret_cast<const char*>(g_Wb2) +                       \
                 (((SP) * 2 + s_) * 24 + n_) * 512 + c_ * 16);                \
        }                                                                     \
        asm volatile("cp.async.commit_group;");                               \
    } while (0)

    float sk = 0.f, ssk = 0.f, sq = 0.f, ssq = 0.f;
    float acc[3][4];

    STAGE_W(0, O_WB0);

    #pragma unroll 1
    for (int p = 0; p < 3; p++) {
        asm volatile("cp.async.wait_group 0;");
        __syncthreads();
        if (p < 2) STAGE_W(p + 1, (p & 1) ? O_WB0 : O_WB1);

        #pragma unroll
        for (int nt = 0; nt < 3; nt++)
            #pragma unroll
            for (int j = 0; j < 4; j++) acc[nt][j] = 0.f;

        const float* base0 = srcs[p] + ((size_t)(b0 + w * 16 + qr) * LDIM + l) * DDIM;
        const float* base1 = base0 + (size_t)8 * LDIM * DDIM;
        const uint32_t* wh = reinterpret_cast<const uint32_t*>(smem + ((p & 1) ? O_WB1 : O_WB0));
        const uint32_t* wl = wh + 3264;

        #pragma unroll 1
        for (int ks4 = 0; ks4 < 4; ks4++) {
            float4 xA[4], xB[4];
            #pragma unroll
            for (int i = 0; i < 4; i++) {
                const int doff = (ks4 * 4 + i) * 16 + 4 * qc;
                xA[i] = *reinterpret_cast<const float4*>(base0 + doff);
                xB[i] = *reinterpret_cast<const float4*>(base1 + doff);
            }
            #pragma unroll
            for (int i = 0; i < 4; i++) {
                uint32_t ah0, al0, ah1, al1, ah2, al2, ah3, al3;
                split2(xA[i].x, xA[i].y, ah0, al0);
                split2(xB[i].x, xB[i].y, ah1, al1);
                split2(xA[i].z, xA[i].w, ah2, al2);
                split2(xB[i].z, xB[i].w, ah3, al3);
                const int kw = (ks4 * 4 + i) * 8 + 2 * qc;
                #pragma unroll
                for (int nt = 0; nt < 3; nt++) {
                    const int bw = (nt * 8 + qr) * 136 + kw;
                    uint2 bh = *reinterpret_cast<const uint2*>(wh + bw);
                    uint2 bl = *reinterpret_cast<const uint2*>(wl + bw);
                    MMA_BF16(acc[nt], ah0, ah1, ah2, ah3, bh.x, bh.y);
                    MMA_BF16(acc[nt], al0, al1, al2, al3, bh.x, bh.y);
                    MMA_BF16(acc[nt], ah0, ah1, ah2, ah3, bl.x, bl.y);
                }
            }
        }

        // epilogue for proj p
        {
            const float* bias = biases[p];
            const int r0 = w * 16 + qr, r1 = r0 + 8;
            #pragma unroll
            for (int nt = 0; nt < 3; nt++) {
                const int c0 = nt * 8 + qc * 2;
                if (c0 < MDIM) {
                    float bb0 = __ldg(bias + c0), bb1 = __ldg(bias + c0 + 1);
                    float v00 = acc[nt][0] + bb0, v01 = acc[nt][1] + bb1;
                    float v10 = acc[nt][2] + bb0, v11 = acc[nt][3] + bb1;
                    if (p == 0) {
                        kt[r0 * MDIM + c0] = v00; kt[r0 * MDIM + c0 + 1] = v01;
                        kt[r1 * MDIM + c0] = v10; kt[r1 * MDIM + c0 + 1] = v11;
                        sk += v00 + v01 + v10 + v11;
                        ssk += v00 * v00 + v01 * v01 + v10 * v10 + v11 * v11;
                    } else if (p == 1) {
                        sq += v00 + v01 + v10 + v11;
                        ssq += v00 * v00 + v01 * v01 + v10 * v10 + v11 * v11;
                        uint32_t h0, l0, h1, l1;
                        split2(v00, v01, h0, l0);
                        split2(v10, v11, h1, l1);
                        size_t i0 = ((size_t)l * BATCH + b0 + r0) * MDIM + c0;
                        size_t i1 = ((size_t)l * BATCH + b0 + r1) * MDIM + c0;
                        *reinterpret_cast<uint32_t*>(g_qsh + i0) = h0;
                        *reinterpret_cast<uint32_t*>(g_qsl + i0) = l0;
                        *reinterpret_cast<uint32_t*>(g_qsh + i1) = h1;
                        *reinterpret_cast<uint32_t*>(g_qsl + i1) = l1;
                    } else {
                        vt[r0 * MDIM + c0] = v00; vt[r0 * MDIM + c0 + 1] = v01;
                        vt[r1 * MDIM + c0] = v10; vt[r1 * MDIM + c0 + 1] = v11;
                    }
                }
            }
        }
    }
#undef STAGE_W
    __syncthreads();

    // ---- kvs partials: warp w reduces rows 16w..16w+15; lanes<20 own m ----
    float* kvp = reinterpret_cast<float*>(smem);   // alias W region: [8][20][20]
    if (lane < MDIM) {
        u64 a[10];
        #pragma unroll
        for (int j = 0; j < 10; j++) a[j] = 0ull;
        #pragma unroll 4
        for (int rr = 0; rr < 16; rr++) {
            int r = w * 16 + rr;
            float km = kt[r * MDIM + lane];
            u64 kk = pack2(km, km);
            const u64* vrow = reinterpret_cast<const u64*>(vt + r * MDIM);
            #pragma unroll
            for (int j = 0; j < 10; j++) a[j] = ffma2(kk, vrow[j], a[j]);
        }
        float2* dst = reinterpret_cast<float2*>(kvp + (w * MDIM + lane) * MDIM);
        #pragma unroll
        for (int j = 0; j < 10; j++) dst[j] = unpack2(a[j]);
    }

    // ---- scalar stats ----
    #pragma unroll
    for (int off = 16; off; off >>= 1) {
        sk  += __shfl_down_sync(0xffffffffu, sk,  off);
        ssk += __shfl_down_sync(0xffffffffu, ssk, off);
        sq  += __shfl_down_sync(0xffffffffu, sq,  off);
        ssq += __shfl_down_sync(0xffffffffu, ssq, off);
    }
    if (lane == 0) { red[w*4+0] = sk; red[w*4+1] = ssk; red[w*4+2] = sq; red[w*4+3] = ssq; }
    __syncthreads();

    if (tid < 4) {
        float s = 0.f;
        #pragma unroll
        for (int ww = 0; ww < 8; ww++) s += red[ww * 4 + tid];
        atomicAdd(&g_scal[(tid + 2) & 3], s);   // 0=sk->2, 1=ssk->3, 2=sq->0, 3=ssq->1
    }
    for (int i = tid; i < MDIM * MDIM; i += 256) {
        float s = 0.f;
        #pragma unroll
        for (int ww = 0; ww < 8; ww++) s += kvp[ww * MDIM * MDIM + i];
        atomicAdd(&g_kvs[l * MDIM * MDIM + i], s);
    }
    if (tid < MDIM) {
        float s1 = 0.f, s2 = 0.f;
        #pragma unroll 8
        for (int r = 0; r < 128; r++) { s1 += kt[r * MDIM + tid]; s2 += vt[r * MDIM + tid]; }
        atomicAdd(&g_ks_sum[l * MDIM + tid], s1);
        atomicAdd(&g_vs_sum[l * MDIM + tid], s2);
    }
}

// ---------------- kernel 2: build g_Pbf (MMA B tiles, alpha folded) + g_C ----------------
__global__ __launch_bounds__(256) void k_mid(const float* __restrict__ Wp) {
    __shared__ float kvs_s[MDIM * MDIM];
    __shared__ float vsum_s[MDIM];
    int l = blockIdx.x, tid = threadIdx.x;
    for (int i = tid; i < MDIM * MDIM; i += 256) kvs_s[i] = g_kvs[l * MDIM * MDIM + i];
    if (tid < MDIM) vsum_s[tid] = g_vs_sum[l * MDIM + tid];
    __syncthreads();
    float sqs = g_scal[0], ssq = g_scal[1], sks = g_scal[2], ssk = g_scal[3];
    float alpha = (sqs != 0.f && sks != 0.f) ? rsqrtf(ssq) * rsqrtf(ssk) : 1.f;
    int d = tid;
    float wp[MDIM];
    #pragma unroll
    for (int m2 = 0; m2 < MDIM; m2++) wp[m2] = __ldg(Wp + m2 * DDIM + d);
    float c = 0.f;
    #pragma unroll
    for (int m2 = 0; m2 < MDIM; m2++) c += vsum_s[m2] * wp[m2];
    g_C[l * DDIM + d] = c;

    float as[MDIM];
    #pragma unroll 4
    for (int m = 0; m < MDIM; m++) {
        float s = 0.f;
        #pragma unroll
        for (int m2 = 0; m2 < MDIM; m2++) s += kvs_s[m * MDIM + m2] * wp[m2];
        as[m] = alpha * s;
    }
    // write B-tile rows: [l][split][kstep][row=d][16]
    #pragma unroll
    for (int split = 0; split < 2; split++)
        #pragma unroll
        for (int kstep = 0; kstep < 2; kstep++) {
            __nv_bfloat16 row[16];
            #pragma unroll
            for (int j = 0; j < 16; j++) {
                int m = kstep * 16 + j;
                float v = (m < MDIM) ? as[m] : 0.f;
                __nv_bfloat16 hi = __float2bfloat16(v);
                row[j] = split ? __float2bfloat16(v - __bfloat162float(hi)) : hi;
            }
            __nv_bfloat16* dst = g_Pbf +
                ((((size_t)l * 2 + split) * 2 + kstep) * 264 + d) * 16;
            *reinterpret_cast<uint4*>(dst) = *reinterpret_cast<uint4*>(row);
            *reinterpret_cast<uint4*>(dst + 8) = *reinterpret_cast<uint4*>(row + 8);
        }
    // extra rows 256..263: row 256 = alpha*ks_sum, rest zero
    if (tid < 8) {
        #pragma unroll
        for (int split = 0; split < 2; split++)
            #pragma unroll
            for (int kstep = 0; kstep < 2; kstep++) {
                __nv_bfloat16 row[16];
                #pragma unroll
                for (int j = 0; j < 16; j++) {
                    int m = kstep * 16 + j;
                    float v = (tid == 0 && m < MDIM) ? alpha * g_ks_sum[l * MDIM + m] : 0.f;
                    __nv_bfloat16 hi = __float2bfloat16(v);
                    row[j] = split ? __float2bfloat16(v - __bfloat162float(hi)) : hi;
                }
                __nv_bfloat16* dst = g_Pbf +
                    ((((size_t)l * 2 + split) * 2 + kstep) * 264 + 256 + tid) * 16;
                *reinterpret_cast<uint4*>(dst) = *reinterpret_cast<uint4*>(row);
                *reinterpret_cast<uint4*>(dst + 8) = *reinterpret_cast<uint4*>(row + 8);
            }
    }
}

// ---------------- kernel 3: output via MMA; normalizer = 33rd d-tile ----------------
// 256 thr (8 warps); block = (l, 128 b). Warp w owns b-rows 16w..16w+15.
// A (qs hi/lo) from gmem LDG.64 k-permuted; B (Pbf) staged in smem.
__global__ __launch_bounds__(256) void k_pass2(float* __restrict__ out,
                                               const float* __restrict__ bp) {
    __shared__ __align__(16) uint32_t Bs[2 * 2 * 264 * 8];   // 33,792 B
    __shared__ float Cs[DDIM];
    __shared__ float bps[DDIM];
    const int tid = threadIdx.x;
    const int w = tid >> 5, lane = tid & 31;
    const int qr = lane >> 2, qc = lane & 3;
    const int l = blockIdx.x, b0 = blockIdx.y * 128;
    uint32_t sbB;
    asm("{ .reg .u64 t; cvta.to.shared.u64 t, %1; cvt.u32.u64 %0, t; }" : "=r"(sbB) : "l"(Bs));

    // stage B tiles for this l (2112 x 16B)
    const char* src = reinterpret_cast<const char*>(g_Pbf) + (size_t)l * 33792;
    #pragma unroll
    for (int i = 0; i < 9; i++) {
        int idx = i * 256 + tid;
        if (idx < 2112) cp16(sbB + (uint32_t)idx * 16, src + idx * 16);
    }
    asm volatile("cp.async.commit_group;");
    Cs[tid] = g_C[l * DDIM + tid];
    bps[tid] = __ldg(bp + tid);
    asm volatile("cp.async.wait_group 0;");
    __syncthreads();

    // A fragments for this warp's 16 b-rows (hi/lo, 2 ksteps, k-permuted)
    const size_t rowi = ((size_t)l * BATCH + b0 + w * 16 + qr) * MDIM;
    const __nv_bfloat16* qh0 = g_qsh + rowi;
    const __nv_bfloat16* qh1 = qh0 + 8 * MDIM;
    const __nv_bfloat16* ql0 = g_qsl + rowi;
    const __nv_bfloat16* ql1 = ql0 + 8 * MDIM;
    uint2 Ah0k0 = *reinterpret_cast<const uint2*>(qh0 + 4 * qc);
    uint2 Ah1k0 = *reinterpret_cast<const uint2*>(qh1 + 4 * qc);
    uint2 Ah0k1 = *reinterpret_cast<const uint2*>(qh0 + 16 + 4 * qc);
    uint2 Ah1k1 = *reinterpret_cast<const uint2*>(qh1 + 16 + 4 * qc);
    uint2 Al0k0 = *reinterpret_cast<const uint2*>(ql0 + 4 * qc);
    uint2 Al1k0 = *reinterpret_cast<const uint2*>(ql1 + 4 * qc);
    uint2 Al0k1 = *reinterpret_cast<const uint2*>(ql0 + 16 + 4 * qc);
    uint2 Al1k1 = *reinterpret_cast<const uint2*>(ql1 + 16 + 4 * qc);

    // smem word offsets: off(split,kstep,row) = ((split*2+kstep)*264 + row)*8
#define BOFF(S, K, ROW) ((((S) * 2 + (K)) * 264 + (ROW)) * 8 + 2 * qc)

    // normalizer tile (rows 256..263; only row 256 nonzero)
    float inv0, inv1;
    {
        float na[4] = {0.f, 0.f, 0.f, 0.f};
        uint2 bh0 = *reinterpret_cast<const uint2*>(Bs + BOFF(0, 0, 256 + qr));
        uint2 bh1 = *reinterpret_cast<const uint2*>(Bs + BOFF(0, 1, 256 + qr));
        uint2 bl0 = *reinterpret_cast<const uint2*>(Bs + BOFF(1, 0, 256 + qr));
        uint2 bl1 = *reinterpret_cast<const uint2*>(Bs + BOFF(1, 1, 256 + qr));
        MMA_BF16(na, Ah0k0.x, Ah1k0.x, Ah0k0.y, Ah1k0.y, bh0.x, bh0.y);
        MMA_BF16(na, Al0k0.x, Al1k0.x, Al0k0.y, Al1k0.y, bh0.x, bh0.y);
        MMA_BF16(na, Ah0k0.x, Ah1k0.x, Ah0k0.y, Ah1k0.y, bl0.x, bl0.y);
        MMA_BF16(na, Ah0k1.x, Ah1k1.x, Ah0k1.y, Ah1k1.y, bh1.x, bh1.y);
        MMA_BF16(na, Al0k1.x, Al1k1.x, Al0k1.y, Al1k1.y, bh1.x, bh1.y);
        MMA_BF16(na, Ah0k1.x, Ah1k1.x, Ah0k1.y, Ah1k1.y, bl1.x, bl1.y);
        float t0 = __shfl_sync(0xffffffffu, na[0], qr * 4);
        float t1 = __shfl_sync(0xffffffffu, na[2], qr * 4);
        inv0 = 1.f / (t0 + (float)BATCH);
        inv1 = 1.f / (t1 + (float)BATCH);
    }

    const size_t ob0 = ((size_t)(b0 + w * 16 + qr) * LDIM + l) * DDIM;
    const size_t ob1 = ob0 + (size_t)8 * LDIM * DDIM;

    #pragma unroll 4
    for (int nt = 0; nt < 32; nt++) {
        const int row = nt * 8 + qr;
        float acc[4] = {0.f, 0.f, 0.f, 0.f};
        uint2 bh0 = *reinterpret_cast<const uint2*>(Bs + BOFF(0, 0, row));
        uint2 bh1 = *reinterpret_cast<const uint2*>(Bs + BOFF(0, 1, row));
        uint2 bl0 = *reinterpret_cast<const uint2*>(Bs + BOFF(1, 0, row));
        uint2 bl1 = *reinterpret_cast<const uint2*>(Bs + BOFF(1, 1, row));
        MMA_BF16(acc, Ah0k0.x, Ah1k0.x, Ah0k0.y, Ah1k0.y, bh0.x, bh0.y);
        MMA_BF16(acc, Al0k0.x, Al1k0.x, Al0k0.y, Al1k0.y, bh0.x, bh0.y);
        MMA_BF16(acc, Ah0k0.x, Ah1k0.x, Ah0k0.y, Ah1k0.y, bl0.x, bl0.y);
        MMA_BF16(acc, Ah0k1.x, Ah1k1.x, Ah0k1.y, Ah1k1.y, bh1.x, bh1.y);
        MMA_BF16(acc, Al0k1.x, Al1k1.x, Al0k1.y, Al1k1.y, bh1.x, bh1.y);
        MMA_BF16(acc, Ah0k1.x, Ah1k1.x, Ah0k1.y, Ah1k1.y, bl1.x, bl1.y);

        const int d0 = nt * 8 + 2 * qc;
        float2 Cp = *reinterpret_cast<const float2*>(Cs + d0);
        float2 bpp = *reinterpret_cast<const float2*>(bps + d0);
        float2 o0, o1;
        o0.x = fmaf(acc[0] + Cp.x, inv0, bpp.x);
        o0.y = fmaf(acc[1] + Cp.y, inv0, bpp.y);
        o1.x = fmaf(acc[2] + Cp.x, inv1, bpp.x);
        o1.y = fmaf(acc[3] + Cp.y, inv1, bpp.y);
        *reinterpret_cast<float2*>(out + ob0 + d0) = o0;
        *reinterpret_cast<float2*>(out + ob1 + d0) = o1;
    }
#undef BOFF
}

// ---------------- launch ----------------
extern "C" void kernel_launch(void* const* d_in, const int* in_sizes, int n_in,
                              void* d_out, int out_size) {
    const float* key   = (const float*)d_in[0];
    const float* value = (const float*)d_in[1];
    const float* query = (const float*)d_in[2];
    const float* Wk = (const float*)d_in[3];
    const float* bk = (const float*)d_in[4];
    const float* Wq = (const float*)d_in[5];
    const float* bq = (const float*)d_in[6];
    const float* Wv = (const float*)d_in[7];
    const float* bv = (const float*)d_in[8];
    const float* Wp = (const float*)d_in[9];
    const float* bp = (const float*)d_in[10];
    float* out = (float*)d_out;
    (void)in_sizes; (void)n_in; (void)out_size;

    cudaFuncSetAttribute(k_pass1, cudaFuncAttributeMaxDynamicSharedMemorySize, SM1_BYTES);

    k_init<<<144, 256>>>(Wk, Wq, Wv);
    k_pass1<<<dim3(LDIM, BATCH / 128), 256, SM1_BYTES>>>(key, query, value, bk, bq, bv);
    k_mid<<<LDIM, 256>>>(Wp);
    k_pass2<<<dim3(LDIM, BATCH / 128), 256>>>(out, bp);
}